// round 12
// baseline (speedup 1.0000x reference)
#include <cuda_runtime.h>
#include <cstdint>

#define RES0 2048
#define RES1 1024
#define NPTS 2097152

// Dup-pair tables: entry (y,x) = codes(y,x) | codes(y,min(x+1,RES-1))<<32.
// One LDG.64 per row fetches both x-corners. 32 MB + 8 MB = 40 MB total.
__device__ uint64_t g_pair0[(size_t)RES0 * RES0];
__device__ uint64_t g_pair1[(size_t)RES1 * RES1];

// codes = clip(round((v + 15/32) * 16), 0, 15); round-half-even matches jnp.round.
__device__ __forceinline__ uint32_t quant_code(float v) {
    float t = __fmul_rn(__fadd_rn(v, 0.46875f), 16.0f);
    int c = __float2int_rn(t);
    return (uint32_t)max(0, min(15, c));
}

// Exact dequant of nibble i: c/16 - 15/32.
__device__ __forceinline__ float dec(uint32_t p, int i) {
    uint32_t t = (i < 5) ? (p << (19 - 4 * i)) : (p >> (4 * i - 19));
    uint32_t u = (t & 0x00780000u) | 0x3F800000u;
    return __uint_as_float(u) - 1.46875f;
}

// ---------------- fused pack: both grids in ONE launch ----------------------
// Tile 32x16 with x-halo in smem; inputs streamed with __ldcs.
template <int RES>
__device__ __forceinline__ void pack_pair(const float* __restrict__ g,
                                          uint64_t* __restrict__ tab, int blk) {
    __shared__ uint32_t sc[16][33];
    int bx = (blk % (RES / 32)) * 32;
    int by = (blk / (RES / 32)) * 16;
    int tid = threadIdx.x;

    for (int p = tid; p < 16 * 33; p += 512) {
        int ly = p / 33, lx = p - ly * 33;
        int gx = min(bx + lx, RES - 1);
        size_t base = (size_t)(by + ly) * RES + gx;
        uint32_t pk = 0;
#pragma unroll
        for (int c = 0; c < 8; c++) {
            float v = __ldcs(g + (size_t)c * RES * RES + base);
            pk |= quant_code(v) << (4 * c);
        }
        sc[ly][lx] = pk;
    }
    __syncthreads();

    int lx = tid & 31, ly = tid >> 5;
    uint64_t e = (uint64_t)sc[ly][lx] | ((uint64_t)sc[ly][lx + 1] << 32);
    tab[(size_t)(by + ly) * RES + bx + lx] = e;
}

#define NBLK0 ((RES0 / 32) * (RES0 / 16))   // 8192
#define NBLK1 ((RES1 / 32) * (RES1 / 16))   // 2048

__global__ __launch_bounds__(512) void pack_all(const float* __restrict__ g0,
                                                const float* __restrict__ g1) {
    int b = blockIdx.x;
    if (b < NBLK0) pack_pair<RES0>(g0, g_pair0, b);
    else           pack_pair<RES1>(g1, g_pair1, b - NBLK0);
}

// ---------------- sample: 4 x LDG.64 gathers per point ----------------------
__global__ __launch_bounds__(256) void sample_kernel(const float2* __restrict__ uv,
                                                     float* __restrict__ out) {
    __shared__ __align__(16) float sbuf[8 * 32 * 12];

    int tid = threadIdx.x;
    int lane = tid & 31;
    int warp = tid >> 5;
    int i = blockIdx.x * 256 + tid;

    float2 p = __ldcs(&uv[i]);

    // feat0: pos = uv*2048 - 0.5 ; x0 = clip(floor(pos), 0, 2046)
    float px = fmaf(p.x, 2048.0f, -0.5f);
    float py = fmaf(p.y, 2048.0f, -0.5f);
    int x0 = min(max((int)floorf(px), 0), RES0 - 2);
    int y0 = min(max((int)floorf(py), 0), RES0 - 2);

    // feat1: ix = u*1024 - 0.5 (== grid_sample formula, exact)
    float ix = fmaf(p.x, 1024.0f, -0.5f);
    float iy = fmaf(p.y, 1024.0f, -0.5f);
    float fx0 = floorf(ix), fy0 = floorf(iy);
    int qx0 = (int)fx0;          // in [-1, 1023]
    int qy0 = (int)fy0;
    int cx  = max(qx0, 0);
    int cy0 = max(qy0, 0);
    int cy1 = min(qy0 + 1, RES1 - 1);   // row of the y1 taps (clamped; masked if OOB)

    // Four independent LDG.64 gathers issued back-to-back.
    const uint64_t* r0 = g_pair0 + (size_t)y0 * RES0 + x0;
    uint64_t e0t = __ldg(r0);
    uint64_t e0b = __ldg(r0 + RES0);
    uint64_t e1t = __ldg(&g_pair1[(size_t)cy0 * RES1 + cx]);
    uint64_t e1b = __ldg(&g_pair1[(size_t)cy1 * RES1 + cx]);

    // feat1 weights (zeros-padding via weight masking).
    float wx1 = __fsub_rn(ix, fx0), wx0 = __fsub_rn(1.0f, wx1);
    float wy1 = __fsub_rn(iy, fy0), wy0 = __fsub_rn(1.0f, wy1);
    float wx0m = (qx0 >= 0) ? wx0 : 0.0f;
    float wx1m = (qx0 + 1 <= RES1 - 1) ? wx1 : 0.0f;
    float wy0m = (qy0 >= 0) ? wy0 : 0.0f;
    float wy1m = (qy0 + 1 <= RES1 - 1) ? wy1 : 0.0f;
    float w00 = wx0m * wy0m;
    float w10 = wx1m * wy0m;
    float w01 = wx0m * wy1m;
    float w11 = wx1m * wy1m;

    // x-slot select: when qx0 == -1, the x1 tap is texel 0 = LOW half.
    uint32_t p00 = (uint32_t)e1t;
    uint32_t p10 = (qx0 < 0) ? (uint32_t)e1t : (uint32_t)(e1t >> 32);
    uint32_t p01 = (uint32_t)e1b;
    uint32_t p11 = (qx0 < 0) ? (uint32_t)e1b : (uint32_t)(e1b >> 32);

    // feat1: FMA accumulation (within ~1e-7 of reference order; tol 1e-3).
    float ff[8];
#pragma unroll
    for (int c = 0; c < 8; c++) {
        float s = dec(p00, c) * w00;
        s = fmaf(dec(p10, c), w10, s);
        s = fmaf(dec(p01, c), w01, s);
        s = fmaf(dec(p11, c), w11, s);
        ff[c] = s;
    }

    // Stage: raw g0 corner codes + decoded feat1 (3x STS.128 per point).
    float* s = &sbuf[warp * (32 * 12) + lane * 12];
    *(uint4*)s = make_uint4((uint32_t)e0t, (uint32_t)(e0t >> 32),
                            (uint32_t)e0b, (uint32_t)(e0b >> 32));
    *(float4*)(s + 4) = make_float4(ff[0], ff[1], ff[2], ff[3]);
    *(float4*)(s + 8) = make_float4(ff[4], ff[5], ff[6], ff[7]);
    __syncwarp();

    // Coalesced readout (evict-first stores protect table residency).
    const float* ws = &sbuf[warp * (32 * 12)];
    float4* go = reinterpret_cast<float4*>(out) +
                 (size_t)(blockIdx.x * 256 + warp * 32) * 10;
#pragma unroll
    for (int k = 0; k < 10; k++) {
        int wo = lane + 32 * k;        // float4 index within the warp's 320
        int pp = wo / 10;              // point within warp tile
        int jj = wo - pp * 10;         // float4 within point
        const float* sp = ws + pp * 12;
        float4 v;
        if (jj < 8) {
            uint32_t code = __float_as_uint(sp[jj >> 1]);  // corner jj>>1
            int cb = (jj & 1) * 4;
            v = make_float4(dec(code, cb), dec(code, cb + 1),
                            dec(code, cb + 2), dec(code, cb + 3));
        } else {
            v = *(const float4*)(sp + 4 + (jj - 8) * 4);   // staged feat1
        }
        __stcs(&go[wo], v);
    }
}

extern "C" void kernel_launch(void* const* d_in, const int* in_sizes, int n_in,
                              void* d_out, int out_size) {
    const float2* uv = (const float2*)d_in[0];
    const float*  g0 = (const float*)d_in[1];
    const float*  g1 = (const float*)d_in[2];

    pack_all<<<NBLK0 + NBLK1, 512>>>(g0, g1);
    sample_kernel<<<NPTS / 256, 256>>>(uv, (float*)d_out);
}

// round 14
// speedup vs baseline: 1.0230x; 1.0230x over previous
#include <cuda_runtime.h>
#include <cstdint>

#define RES0 2048
#define RES1 1024
#define NPTS 2097152

// g0: plain per-texel code table (8ch x 4bit -> u32). 16 MB.
__device__ uint32_t g_code0[(size_t)RES0 * RES0];
// g1: quad table, entry (y,x) = codes of 4 clamped corners. 16 MB.
__device__ uint4 g_quad1[(size_t)RES1 * RES1];
// Total 32 MB -> L2-resident against evict-first streams (proven in R11).

// codes = clip(round((v + 15/32) * 16), 0, 15); round-half-even matches jnp.round.
__device__ __forceinline__ uint32_t quant_code(float v) {
    float t = __fmul_rn(__fadd_rn(v, 0.46875f), 16.0f);
    int c = __float2int_rn(t);
    return (uint32_t)max(0, min(15, c));
}

// Exact dequant of nibble i: c/16 - 15/32.
__device__ __forceinline__ float dec(uint32_t p, int i) {
    uint32_t t = (i < 5) ? (p << (19 - 4 * i)) : (p >> (4 * i - 19));
    uint32_t u = (t & 0x00780000u) | 0x3F800000u;
    return __uint_as_float(u) - 1.46875f;
}

// ---------------- fused pack: both grids in ONE launch ----------------------
// g0: pure streaming quantize (no halo), 4 texels/thread, vectorized.
__device__ __forceinline__ void pack_body0(const float* __restrict__ g, int blk) {
    int i4 = (blk * 512 + threadIdx.x) * 4;
    uint32_t c0 = 0, c1 = 0, c2 = 0, c3 = 0;
#pragma unroll
    for (int ch = 0; ch < 8; ch++) {
        float4 v = __ldcs((const float4*)(g + (size_t)ch * RES0 * RES0 + i4));
        c0 |= quant_code(v.x) << (4 * ch);
        c1 |= quant_code(v.y) << (4 * ch);
        c2 |= quant_code(v.z) << (4 * ch);
        c3 |= quant_code(v.w) << (4 * ch);
    }
    *(uint4*)(g_code0 + i4) = make_uint4(c0, c1, c2, c3);
}

// g1: full quad (x+y halo) via smem tile.
__device__ __forceinline__ void pack_body1(const float* __restrict__ g, int blk) {
    __shared__ uint32_t sc[17][33];
    int bx = (blk % (RES1 / 32)) * 32;
    int by = (blk / (RES1 / 32)) * 16;
    int tid = threadIdx.x;

    for (int p = tid; p < 17 * 33; p += 512) {
        int ly = p / 33, lx = p - ly * 33;
        int gx = min(bx + lx, RES1 - 1);
        int gy = min(by + ly, RES1 - 1);
        size_t base = (size_t)gy * RES1 + gx;
        uint32_t pk = 0;
#pragma unroll
        for (int c = 0; c < 8; c++) {
            float v = __ldcs(g + (size_t)c * RES1 * RES1 + base);
            pk |= quant_code(v) << (4 * c);
        }
        sc[ly][lx] = pk;
    }
    __syncthreads();

    int lx = tid & 31, ly = tid >> 5;
    g_quad1[(size_t)(by + ly) * RES1 + bx + lx] =
        make_uint4(sc[ly][lx], sc[ly][lx + 1], sc[ly + 1][lx], sc[ly + 1][lx + 1]);
}

#define NBLK0 (RES0 * RES0 / 4 / 512)       // 2048
#define NBLK1 ((RES1 / 32) * (RES1 / 16))   // 2048

__global__ __launch_bounds__(512) void pack_all(const float* __restrict__ g0,
                                                const float* __restrict__ g1) {
    int b = blockIdx.x;
    if (b < NBLK0) pack_body0(g0, b);
    else           pack_body1(g1, b - NBLK0);
}

// ---------------- sample: L2-only gathers, 256-bit stores -------------------
__global__ __launch_bounds__(256) void sample_kernel(const float2* __restrict__ uv,
                                                     float* __restrict__ out) {
    __shared__ __align__(16) float sbuf[8 * 32 * 12];

    int tid = threadIdx.x;
    int lane = tid & 31;
    int warp = tid >> 5;
    int i = blockIdx.x * 256 + tid;

    float2 p = __ldcs(&uv[i]);

    // feat0: pos = uv*2048 - 0.5 ; x0 = clip(floor(pos), 0, 2046)
    float px = fmaf(p.x, 2048.0f, -0.5f);
    float py = fmaf(p.y, 2048.0f, -0.5f);
    int x0 = min(max((int)floorf(px), 0), RES0 - 2);
    int y0 = min(max((int)floorf(py), 0), RES0 - 2);

    // feat1: ix = u*1024 - 0.5 (== grid_sample formula, exact)
    float ix = fmaf(p.x, 1024.0f, -0.5f);
    float iy = fmaf(p.y, 1024.0f, -0.5f);
    float fx0 = floorf(ix), fy0 = floorf(iy);
    int qx0 = (int)fx0;
    int qy0 = (int)fy0;
    int cx = max(qx0, 0);
    int cy = max(qy0, 0);

    // Five independent gathers, L2-only (.cg) -> no 128B L1 line fills.
    const uint32_t* c0 = g_code0 + (size_t)y0 * RES0 + x0;
    uint32_t a00 = __ldcg(c0);
    uint32_t a01 = __ldcg(c0 + 1);
    uint32_t a10 = __ldcg(c0 + RES0);
    uint32_t a11 = __ldcg(c0 + RES0 + 1);
    uint4 q1 = __ldcg(&g_quad1[(size_t)cy * RES1 + cx]);

    // feat1 weights (zeros-padding via weight masking).
    float wx1 = __fsub_rn(ix, fx0), wx0 = __fsub_rn(1.0f, wx1);
    float wy1 = __fsub_rn(iy, fy0), wy0 = __fsub_rn(1.0f, wy1);
    float wx0m = (qx0 >= 0) ? wx0 : 0.0f;
    float wx1m = (qx0 + 1 <= RES1 - 1) ? wx1 : 0.0f;
    float wy0m = (qy0 >= 0) ? wy0 : 0.0f;
    float wy1m = (qy0 + 1 <= RES1 - 1) ? wy1 : 0.0f;
    float w00 = wx0m * wy0m;
    float w10 = wx1m * wy0m;
    float w01 = wx0m * wy1m;
    float w11 = wx1m * wy1m;

    // Slot-select for clamped/OOB taps.
    uint32_t p00 = q1.x;
    uint32_t p10 = (qx0 < 0) ? q1.x : q1.y;
    uint32_t p01 = (qy0 < 0) ? q1.x : q1.z;
    uint32_t p11 = (qy0 < 0) ? ((qx0 < 0) ? q1.x : q1.y)
                             : ((qx0 < 0) ? q1.z : q1.w);

    // feat1: FMA accumulation (within ~1e-7 of reference order; tol 1e-3).
    float ff[8];
#pragma unroll
    for (int c = 0; c < 8; c++) {
        float s = dec(p00, c) * w00;
        s = fmaf(dec(p10, c), w10, s);
        s = fmaf(dec(p01, c), w01, s);
        s = fmaf(dec(p11, c), w11, s);
        ff[c] = s;
    }

    // Stage: raw g0 corner codes + decoded feat1 (3x STS.128 per point).
    float* s = &sbuf[warp * (32 * 12) + lane * 12];
    *(uint4*)s = make_uint4(a00, a01, a10, a11);
    *(float4*)(s + 4) = make_float4(ff[0], ff[1], ff[2], ff[3]);
    *(float4*)(s + 8) = make_float4(ff[4], ff[5], ff[6], ff[7]);
    __syncwarp();

    // Coalesced readout: each lane emits one 32B float8 (st.global.cs.v8.f32).
    // Warp region = 32 points * 40 floats = 160 float8s = 5 iterations.
    const float* ws = &sbuf[warp * (32 * 12)];
    float* gob = out + (size_t)(blockIdx.x * 256 + warp * 32) * 40;
#pragma unroll
    for (int k = 0; k < 5; k++) {
        int wo = lane + 32 * k;        // float8 index within 160
        int pp = wo / 5;               // point within warp tile
        int jj = wo - pp * 5;          // float8 within point: 0-3 = corners, 4 = feat1
        const float* sp = ws + pp * 12;
        float v0, v1, v2, v3, v4, v5, v6, v7;
        if (jj < 4) {
            uint32_t code = __float_as_uint(sp[jj]);   // one corner's 8 channels
            v0 = dec(code, 0); v1 = dec(code, 1);
            v2 = dec(code, 2); v3 = dec(code, 3);
            v4 = dec(code, 4); v5 = dec(code, 5);
            v6 = dec(code, 6); v7 = dec(code, 7);
        } else {
            float4 a = *(const float4*)(sp + 4);
            float4 b = *(const float4*)(sp + 8);
            v0 = a.x; v1 = a.y; v2 = a.z; v3 = a.w;
            v4 = b.x; v5 = b.y; v6 = b.z; v7 = b.w;
        }
        asm volatile(
            "st.global.cs.v8.f32 [%0], {%1,%2,%3,%4,%5,%6,%7,%8};"
            :: "l"(gob + (size_t)wo * 8),
               "f"(v0), "f"(v1), "f"(v2), "f"(v3),
               "f"(v4), "f"(v5), "f"(v6), "f"(v7)
            : "memory");
    }
}

extern "C" void kernel_launch(void* const* d_in, const int* in_sizes, int n_in,
                              void* d_out, int out_size) {
    const float2* uv = (const float2*)d_in[0];
    const float*  g0 = (const float*)d_in[1];
    const float*  g1 = (const float*)d_in[2];

    pack_all<<<NBLK0 + NBLK1, 512>>>(g0, g1);
    sample_kernel<<<NPTS / 256, 256>>>(uv, (float*)d_out);
}

// round 15
// speedup vs baseline: 1.1146x; 1.0895x over previous
#include <cuda_runtime.h>
#include <cstdint>

#define RES0 2048
#define RES1 1024
#define NPTS 2097152

// g0: plain per-texel code table (8ch x 4bit -> u32). 16 MB.
__device__ uint32_t g_code0[(size_t)RES0 * RES0];
// g1: quad table, entry (y,x) = codes of 4 clamped corners. 16 MB.
__device__ uint4 g_quad1[(size_t)RES1 * RES1];
// Total 32 MB -> fully L2-resident against evict-first streams (proven R11).

// codes = clip(round((v + 15/32) * 16), 0, 15); round-half-even matches jnp.round.
__device__ __forceinline__ uint32_t quant_code(float v) {
    float t = __fmul_rn(__fadd_rn(v, 0.46875f), 16.0f);
    int c = __float2int_rn(t);
    return (uint32_t)max(0, min(15, c));
}

// Exact dequant of nibble i: c/16 - 15/32.
__device__ __forceinline__ float dec(uint32_t p, int i) {
    uint32_t t = (i < 5) ? (p << (19 - 4 * i)) : (p >> (4 * i - 19));
    uint32_t u = (t & 0x00780000u) | 0x3F800000u;
    return __uint_as_float(u) - 1.46875f;
}

// Partial dequant: 1 + c/16 (no subtraction). SHF + LOP3 only.
__device__ __forceinline__ float decu(uint32_t p, int i) {
    uint32_t t = (i < 5) ? (p << (19 - 4 * i)) : (p >> (4 * i - 19));
    uint32_t u = (t & 0x00780000u) | 0x3F800000u;
    return __uint_as_float(u);
}

// ---------------- fused pack: both grids in ONE launch ----------------------
// g0: pure streaming quantize (no halo), 4 texels/thread, vectorized.
__device__ __forceinline__ void pack_body0(const float* __restrict__ g, int blk) {
    int i4 = (blk * 512 + threadIdx.x) * 4;
    uint32_t c0 = 0, c1 = 0, c2 = 0, c3 = 0;
#pragma unroll
    for (int ch = 0; ch < 8; ch++) {
        float4 v = __ldcs((const float4*)(g + (size_t)ch * RES0 * RES0 + i4));
        c0 |= quant_code(v.x) << (4 * ch);
        c1 |= quant_code(v.y) << (4 * ch);
        c2 |= quant_code(v.z) << (4 * ch);
        c3 |= quant_code(v.w) << (4 * ch);
    }
    *(uint4*)(g_code0 + i4) = make_uint4(c0, c1, c2, c3);
}

// g1: full quad (x+y halo) via smem tile.
__device__ __forceinline__ void pack_body1(const float* __restrict__ g, int blk) {
    __shared__ uint32_t sc[17][33];
    int bx = (blk % (RES1 / 32)) * 32;
    int by = (blk / (RES1 / 32)) * 16;
    int tid = threadIdx.x;

    for (int p = tid; p < 17 * 33; p += 512) {
        int ly = p / 33, lx = p - ly * 33;
        int gx = min(bx + lx, RES1 - 1);
        int gy = min(by + ly, RES1 - 1);
        size_t base = (size_t)gy * RES1 + gx;
        uint32_t pk = 0;
#pragma unroll
        for (int c = 0; c < 8; c++) {
            float v = __ldcs(g + (size_t)c * RES1 * RES1 + base);
            pk |= quant_code(v) << (4 * c);
        }
        sc[ly][lx] = pk;
    }
    __syncthreads();

    int lx = tid & 31, ly = tid >> 5;
    g_quad1[(size_t)(by + ly) * RES1 + bx + lx] =
        make_uint4(sc[ly][lx], sc[ly][lx + 1], sc[ly + 1][lx], sc[ly + 1][lx + 1]);
}

#define NBLK0 (RES0 * RES0 / 4 / 512)       // 2048
#define NBLK1 ((RES1 / 32) * (RES1 / 16))   // 2048

__global__ __launch_bounds__(512) void pack_all(const float* __restrict__ g0,
                                                const float* __restrict__ g1) {
    int b = blockIdx.x;
    if (b < NBLK0) pack_body0(g0, b);
    else           pack_body1(g1, b - NBLK0);
}

// ---------------- sample: R11 structure + reduced-ALU feat1 -----------------
__global__ __launch_bounds__(256) void sample_kernel(const float2* __restrict__ uv,
                                                     float* __restrict__ out) {
    __shared__ __align__(16) float sbuf[8 * 32 * 12];

    int tid = threadIdx.x;
    int lane = tid & 31;
    int warp = tid >> 5;
    int i = blockIdx.x * 256 + tid;

    float2 p = __ldcs(&uv[i]);

    // feat1 indices first (its gather is the earliest consumer).
    float ix = fmaf(p.x, 1024.0f, -0.5f);
    float iy = fmaf(p.y, 1024.0f, -0.5f);
    float fx0 = floorf(ix), fy0 = floorf(iy);
    int qx0 = (int)fx0;
    int qy0 = (int)fy0;
    int cx = max(qx0, 0);
    int cy = max(qy0, 0);

    // feat0 indices: pos = uv*2048 - 0.5 ; x0 = clip(floor(pos), 0, 2046)
    float px = fmaf(p.x, 2048.0f, -0.5f);
    float py = fmaf(p.y, 2048.0f, -0.5f);
    int x0 = min(max((int)floorf(px), 0), RES0 - 2);
    int y0 = min(max((int)floorf(py), 0), RES0 - 2);

    // Five independent gathers, q1 first.
    uint4 q1 = __ldg(&g_quad1[(size_t)cy * RES1 + cx]);
    const uint32_t* c0 = g_code0 + (size_t)y0 * RES0 + x0;
    uint32_t a00 = __ldg(c0);
    uint32_t a01 = __ldg(c0 + 1);
    uint32_t a10 = __ldg(c0 + RES0);
    uint32_t a11 = __ldg(c0 + RES0 + 1);

    // feat1 weights (zeros-padding via weight masking).
    float wx1 = __fsub_rn(ix, fx0), wx0 = __fsub_rn(1.0f, wx1);
    float wy1 = __fsub_rn(iy, fy0), wy0 = __fsub_rn(1.0f, wy1);
    float wx0m = (qx0 >= 0) ? wx0 : 0.0f;
    float wx1m = (qx0 + 1 <= RES1 - 1) ? wx1 : 0.0f;
    float wy0m = (qy0 >= 0) ? wy0 : 0.0f;
    float wy1m = (qy0 + 1 <= RES1 - 1) ? wy1 : 0.0f;
    float w00 = wx0m * wy0m;
    float w10 = wx1m * wy0m;
    float w01 = wx0m * wy1m;
    float w11 = wx1m * wy1m;
    // Dequant refactor: sum_c (u_i - k) w_i = sum u_i w_i - k * sum w_i,
    // with u_i = 1 + c_i/16 and k = 1.46875. base computed ONCE per point.
    float wsum = ((w00 + w10) + w01) + w11;
    float base = -1.46875f * wsum;

    // Slot-select for clamped/OOB taps.
    uint32_t p00 = q1.x;
    uint32_t p10 = (qx0 < 0) ? q1.x : q1.y;
    uint32_t p01 = (qy0 < 0) ? q1.x : q1.z;
    uint32_t p11 = (qy0 < 0) ? ((qx0 < 0) ? q1.x : q1.y)
                             : ((qx0 < 0) ? q1.z : q1.w);

    // feat1: 8 channels, 4-FMA chain from base (no per-tap dequant subtract).
    float ff[8];
#pragma unroll
    for (int c = 0; c < 8; c++) {
        float s = fmaf(decu(p11, c), w11, base);
        s = fmaf(decu(p01, c), w01, s);
        s = fmaf(decu(p10, c), w10, s);
        s = fmaf(decu(p00, c), w00, s);
        ff[c] = s;
    }

    // Stage: raw g0 corner codes + decoded feat1 (3x STS.128 per point).
    float* s = &sbuf[warp * (32 * 12) + lane * 12];
    *(uint4*)s = make_uint4(a00, a01, a10, a11);
    *(float4*)(s + 4) = make_float4(ff[0], ff[1], ff[2], ff[3]);
    *(float4*)(s + 8) = make_float4(ff[4], ff[5], ff[6], ff[7]);
    __syncwarp();

    // Coalesced readout: decode feat0 nibbles on the fly.
    const float* ws = &sbuf[warp * (32 * 12)];
    float4* go = reinterpret_cast<float4*>(out) +
                 (size_t)(blockIdx.x * 256 + warp * 32) * 10;
#pragma unroll
    for (int k = 0; k < 10; k++) {
        int wo = lane + 32 * k;        // float4 index within the warp's 320
        int pp = wo / 10;              // point within warp tile
        int jj = wo - pp * 10;         // float4 within point
        const float* sp = ws + pp * 12;
        float4 v;
        if (jj < 8) {
            uint32_t code = __float_as_uint(sp[jj >> 1]);  // corner jj>>1
            int cb = (jj & 1) * 4;
            v = make_float4(dec(code, cb), dec(code, cb + 1),
                            dec(code, cb + 2), dec(code, cb + 3));
        } else {
            v = *(const float4*)(sp + 4 + (jj - 8) * 4);   // staged feat1
        }
        __stcs(&go[wo], v);
    }
}

extern "C" void kernel_launch(void* const* d_in, const int* in_sizes, int n_in,
                              void* d_out, int out_size) {
    const float2* uv = (const float2*)d_in[0];
    const float*  g0 = (const float*)d_in[1];
    const float*  g1 = (const float*)d_in[2];

    pack_all<<<NBLK0 + NBLK1, 512>>>(g0, g1);
    sample_kernel<<<NPTS / 256, 256>>>(uv, (float*)d_out);
}